// round 16
// baseline (speedup 1.0000x reference)
#include <cuda_runtime.h>
#include <cstdint>

#define V_     10000
#define VPAD   10240
#define E_     128
#define NTOK   2048
#define NR     8
#define NW     1250          // class words per token (V_/8)
#define NWP    1280          // padded words per token (VPAD/8)

#define KSPLIT 20
#define KQ     512           // 20*512 = 10240 = VPAD exactly

// ---------------- scratch (device globals; no allocations) ----------------
__device__ float    g_base[(size_t)NTOK * VPAD];     // q = exp(base)-1 (pad cols = 0)
__device__ uint32_t g_cls4[(size_t)NTOK * NWP];      // 4-bit classes, 8/word; pad = 0
__device__ float    g_colsum[E_];
__device__ float    g_part[40 * E_];
__device__ float    g_stats[NTOK * 12];              // K1[8], beta
__device__ float    g_psum[KSPLIT][(size_t)NTOK * E_];

__device__ __forceinline__ void fma2(unsigned long long& acc,
                                     unsigned long long a, unsigned long long b) {
    asm("fma.rn.f32x2 %0, %1, %2, %0;" : "+l"(acc) : "l"(a), "l"(b));
}
__device__ __forceinline__ unsigned long long dup2(float x) {
    unsigned long long r;
    asm("mov.b64 %0, {%1, %1};" : "=l"(r) : "r"(__float_as_uint(x)));
    return r;
}

// ---------------- column sums of W (deterministic 2-stage) ----------------
__global__ void k_colsum1(const float* __restrict__ W) {
    int b = blockIdx.x, col = threadIdx.x;
    float s = 0.f;
    int v0 = b * 250;
    for (int v = v0; v < v0 + 250; v++) s += W[v * E_ + col];
    g_part[b * E_ + col] = s;
}
__global__ void k_colsum2() {
    int col = threadIdx.x;
    float s = 0.f;
    for (int b = 0; b < 40; b++) s += g_part[b * E_ + col];
    g_colsum[col] = s;
}

// ---------------- classification: rel/edge -> packed 4-bit classes ----------------
__global__ __launch_bounds__(256) void k_classify(
    const int*   __restrict__ src,
    const float* __restrict__ edge,
    const int*   __restrict__ rel)
{
    int idx = blockIdx.x * 256 + threadIdx.x;
    int t = idx / NW;
    int w = idx - t * NW;
    long s = src[t];
    int v0 = w * 8;
    const int*   rp = rel  + s * (long)V_ + v0;
    const float* ep = edge + s * (long)V_ + v0;
    uint32_t pack = 0;
#pragma unroll
    for (int h = 0; h < 2; h++) {
        int4   r4 = *(const int4*)  (rp + 4 * h);
        float4 e4 = *(const float4*)(ep + 4 * h);
        uint32_t cx = (r4.x >= 1 && r4.x <= 8 && e4.x > 0.f) ? (uint32_t)r4.x : 0u;
        uint32_t cy = (r4.y >= 1 && r4.y <= 8 && e4.y > 0.f) ? (uint32_t)r4.y : 0u;
        uint32_t cz = (r4.z >= 1 && r4.z <= 8 && e4.z > 0.f) ? (uint32_t)r4.z : 0u;
        uint32_t cw = (r4.w >= 1 && r4.w <= 8 && e4.w > 0.f) ? (uint32_t)r4.w : 0u;
        pack |= (cx | (cy << 4) | (cz << 8) | (cw << 12)) << (16 * h);
    }
    g_cls4[(size_t)t * NWP + w] = pack;
}

// ============== FMA-bound FFMA2 GEMM machinery ==============
// CTA: 128 tokens x 128 cols, 128 threads, 8 tok x 16 col per thread.
// tx = tid & 7  (cols 16*tx .. 16*tx+15), ty = tid >> 3 (tokens 8*ty .. 8*ty+7).
// W rows [kk][128]: 4 LDS.128 per thread-kk (16 wf/warp-kk).
// A rows [kk][132] UNduplicated: 8 LDS.32 (+reg dup) per thread-kk (8 wf/warp-kk).
// Per CTA-kk: LSU 96 cyc < fma 128 cyc -> FMA-bound.
#define KC 16
#define AW 132

#define GEMM_INNER(Wb, Ab, buf)                                              \
    _Pragma("unroll")                                                        \
    for (int kk = 0; kk < KC; kk++) {                                        \
        const float* wrow = &(Wb)[((buf) * KC + kk) * 128 + 16 * tx];        \
        const float* arow = &(Ab)[((buf) * KC + kk) * AW + 8 * ty];          \
        ulonglong2 w01 = *(const ulonglong2*)(wrow);                         \
        ulonglong2 w23 = *(const ulonglong2*)(wrow + 4);                     \
        ulonglong2 w45 = *(const ulonglong2*)(wrow + 8);                     \
        ulonglong2 w67 = *(const ulonglong2*)(wrow + 12);                    \
        unsigned long long wv[8] = {w01.x, w01.y, w23.x, w23.y,              \
                                    w45.x, w45.y, w67.x, w67.y};             \
        _Pragma("unroll")                                                    \
        for (int i = 0; i < 8; i++) {                                        \
            unsigned long long av = dup2(arow[i]);                           \
            _Pragma("unroll")                                                \
            for (int j = 0; j < 8; j++)                                      \
                fma2(acc[i][j], av, wv[j]);                                  \
        }                                                                    \
    }

// ---------------- base GEMM: q = exp(X @ W^T) - 1 ----------------
#define BAS_OFF   (2 * KC * 128)
#define BASE_SMEM ((BAS_OFF + 2 * KC * AW) * 4)     // 33280 B

__global__ __launch_bounds__(128, 2) void k_base(
    const float* __restrict__ X,
    const float* __restrict__ W)
{
    extern __shared__ float smb[];
    float* Wb = smb;               // [buf*16 + kk][128]  kk = e index, col = v
    float* Ab = smb + BAS_OFF;     // [buf*16 + kk][132]  128 tokens, no dup

    int tid  = threadIdx.x;
    int vblk = blockIdx.x * 128;
    int t0   = blockIdx.y * 128;
    int tx = tid & 7, ty = tid >> 3;
    int gvW = vblk + tid;

    unsigned long long acc[8][8];
#pragma unroll
    for (int i = 0; i < 8; i++)
#pragma unroll
        for (int j = 0; j < 8; j++) acc[i][j] = 0ull;

    float4 wst[4], xst[4];
    auto stage = [&](int kc) {
#pragma unroll
        for (int j = 0; j < 4; j++)
            wst[j] = (gvW < V_) ? *(const float4*)&W[(size_t)gvW * E_ + kc + 4 * j]
                                : make_float4(0.f, 0.f, 0.f, 0.f);
#pragma unroll
        for (int j = 0; j < 4; j++)
            xst[j] = *(const float4*)&X[(size_t)(t0 + tid) * E_ + kc + 4 * j];
    };
    auto commit = [&](int buf) {
        // W transpose: row = e (kk), col = v (tid); contiguous per instr
#pragma unroll
        for (int j = 0; j < 4; j++) {
            float* wr = &Wb[(buf * KC + 4 * j) * 128 + tid];
            wr[0]   = wst[j].x;
            wr[128] = wst[j].y;
            wr[256] = wst[j].z;
            wr[384] = wst[j].w;
        }
        // A transpose: row = e (kk), col = token (tid)
        float xs[16];
#pragma unroll
        for (int m = 0; m < 4; m++) {
            xs[4*m+0] = xst[m].x; xs[4*m+1] = xst[m].y;
            xs[4*m+2] = xst[m].z; xs[4*m+3] = xst[m].w;
        }
#pragma unroll
        for (int m = 0; m < 16; m++)
            Ab[(buf * KC + m) * AW + tid] = xs[m];
    };

    stage(0);
    commit(0);
    int buf = 0;
    for (int ch = 0; ch < E_ / KC; ch++) {       // 8 chunks
        __syncthreads();
        if (ch + 1 < E_ / KC) stage((ch + 1) * KC);
        GEMM_INNER(Wb, Ab, buf);
        if (ch + 1 < E_ / KC) commit(buf ^ 1);
        buf ^= 1;
    }

#pragma unroll
    for (int i = 0; i < 8; i++) {
        int t = t0 + 8 * ty + i;
#pragma unroll
        for (int m = 0; m < 4; m++) {
            float2 lo = *(float2*)&acc[i][2 * m];
            float2 hi = *(float2*)&acc[i][2 * m + 1];
            float4 q = make_float4(__expf(lo.x) - 1.f, __expf(lo.y) - 1.f,
                                   __expf(hi.x) - 1.f, __expf(hi.y) - 1.f);
            *(float4*)&g_base[(size_t)t * VPAD + vblk + 16 * tx + 4 * m] = q;
        }
    }
}

// ---------------- per-(t,r) stats: 2-copy lane-private smem RMW ----------------
#define CSTRIDE 33

__global__ __launch_bounds__(256) void k_stats() {
    __shared__ float2 accs[2][8][9 * CSTRIDE];
    __shared__ float  eArr[NR], dArr[NR], Bsh[8];

    int t   = blockIdx.x;
    int tid = threadIdx.x;
    int w   = tid >> 5, lane = tid & 31;

    for (int i = tid; i < 2 * 8 * 9 * CSTRIDE; i += 256)
        ((float2*)accs)[i] = make_float2(0.f, 0.f);
    __syncthreads();

    float B = 0.f;
    const float*    qRow = g_base + (size_t)t * VPAD;
    const uint32_t* cRow = g_cls4 + (size_t)t * NWP;

    for (int i = tid; i < NW; i += 256) {
        float4 qa = *(const float4*)(qRow + 8 * i);
        float4 qb = *(const float4*)(qRow + 8 * i + 4);
        uint32_t cw = cRow[i];
        float qs[8] = {qa.x, qa.y, qa.z, qa.w, qb.x, qb.y, qb.z, qb.w};
#pragma unroll
        for (int j = 0; j < 8; j++) {
            float q = qs[j];
            int   c = (cw >> (4 * j)) & 15;
            float b = __logf(fmaxf(q + 1.f, 1e-38f));
            B += b;
            float2* p = &accs[j & 1][w][c * CSTRIDE + lane];
            float2 o = *p;
            o.x += q;
            o.y = fmaf(q, b, o.y);
            *p = o;
        }
    }
#pragma unroll
    for (int o = 16; o; o >>= 1) B += __shfl_xor_sync(0xFFFFFFFFu, B, o);
    if (lane == 0) Bsh[w] = B;
    __syncthreads();

    {
        float2 s = make_float2(0.f, 0.f);
#pragma unroll
        for (int ww = 0; ww < 8; ww++) {
            float2 a0 = accs[0][ww][(w + 1) * CSTRIDE + lane];
            float2 a1 = accs[1][ww][(w + 1) * CSTRIDE + lane];
            s.x += a0.x + a1.x;
            s.y += a0.y + a1.y;
        }
#pragma unroll
        for (int o = 16; o; o >>= 1) {
            s.x += __shfl_xor_sync(0xFFFFFFFFu, s.x, o);
            s.y += __shfl_xor_sync(0xFFFFFFFFu, s.y, o);
        }
        if (lane == 0) { eArr[w] = s.x; dArr[w] = s.y; }
    }
    __syncthreads();

    if (tid == 0) {
        float Bt = 0.f;
#pragma unroll
        for (int k = 0; k < 8; k++) Bt += Bsh[k];
        float sc[NR], Zv[NR];
#pragma unroll
        for (int r = 0; r < NR; r++) {
            float Z = (float)V_ + eArr[r];
            Zv[r] = Z;
            sc[r] = (dArr[r] + Bt) / Z;
        }
        float mx = sc[0];
#pragma unroll
        for (int r = 1; r < NR; r++) mx = fmaxf(mx, sc[r]);
        float es[NR], ss = 0.f;
#pragma unroll
        for (int r = 0; r < NR; r++) { es[r] = __expf(sc[r] - mx); ss += es[r]; }
        float inv = 1.f / ss;
        float beta = 0.f;
        float* st = g_stats + t * 12;
#pragma unroll
        for (int r = 0; r < NR; r++) {
            float K1 = es[r] * inv / Zv[r];
            st[r] = K1;
            beta += K1;
        }
        st[8] = beta;
    }
}

// ---------------- final GEMM: psum = gamma @ W (gamma = K1[c]*q on the fly) ----------------
#define FK1_OFF  (BAS_OFF + 2 * KC * AW)
#define FIN_SMEM ((FK1_OFF + 8 * 128) * 4)          // 37376 B

__global__ __launch_bounds__(128, 2) void k_final(const float* __restrict__ W) {
    extern __shared__ float smf[];
    float* Wb  = smf;              // [buf*16 + kk][128]  kk = v index, col = e
    float* Ab  = smf + BAS_OFF;    // [buf*16 + kk][132]  gamma, 128 tokens
    float* K1s = smf + FK1_OFF;    // [r][128] transposed

    int tid = threadIdx.x;
    int t0  = blockIdx.x * 128;
    int ks  = blockIdx.y;
    int k0  = ks * KQ;
    int tx = tid & 7, ty = tid >> 3;

    {
        float4 k1a = *(const float4*)&g_stats[(t0 + tid) * 12];
        float4 k1b = *(const float4*)&g_stats[(t0 + tid) * 12 + 4];
        K1s[0 * 128 + tid] = k1a.x; K1s[1 * 128 + tid] = k1a.y;
        K1s[2 * 128 + tid] = k1a.z; K1s[3 * 128 + tid] = k1a.w;
        K1s[4 * 128 + tid] = k1b.x; K1s[5 * 128 + tid] = k1b.y;
        K1s[6 * 128 + tid] = k1b.z; K1s[7 * 128 + tid] = k1b.w;
    }
    __syncthreads();

    unsigned long long acc[8][8];
#pragma unroll
    for (int i = 0; i < 8; i++)
#pragma unroll
        for (int j = 0; j < 8; j++) acc[i][j] = 0ull;

    float4   wst[4], qst[4];
    uint2    cst;

    auto stage = [&](int kc) {   // kc = global v offset of chunk
#pragma unroll
        for (int j = 0; j < 4; j++) {
            int p  = tid + 128 * j;
            int v  = p >> 5;
            int e4 = (p & 31) * 4;
            int gv = kc + v;
            wst[j] = (gv < V_) ? *(const float4*)&W[(size_t)gv * E_ + e4]
                               : make_float4(0.f, 0.f, 0.f, 0.f);
        }
        size_t off = (size_t)(t0 + tid) * VPAD + kc;
#pragma unroll
        for (int m = 0; m < 4; m++)
            qst[m] = *(const float4*)(g_base + off + 4 * m);
        cst = *(const uint2*)(g_cls4 + (size_t)(t0 + tid) * NWP + (kc >> 3));
    };
    auto commit = [&](int buf) {
#pragma unroll
        for (int j = 0; j < 4; j++) {
            int p  = tid + 128 * j;
            int v  = p >> 5;
            int e4 = (p & 31) * 4;
            *(float4*)&Wb[(buf * KC + v) * 128 + e4] = wst[j];
        }
        float qs[16];
#pragma unroll
        for (int m = 0; m < 4; m++) {
            qs[4*m+0] = qst[m].x; qs[4*m+1] = qst[m].y;
            qs[4*m+2] = qst[m].z; qs[4*m+3] = qst[m].w;
        }
#pragma unroll
        for (int m = 0; m < 16; m++) {
            uint32_t word = (m < 8) ? cst.x : cst.y;
            int cc = (word >> (4 * (m & 7))) & 15;
            float g = cc ? K1s[(cc - 1) * 128 + tid] * qs[m] : 0.f;
            Ab[(buf * KC + m) * AW + tid] = g;
        }
    };

    stage(k0);
    commit(0);
    int buf = 0;
    const int NCH = KQ / KC;     // 32
    for (int ch = 0; ch < NCH; ch++) {
        __syncthreads();
        if (ch + 1 < NCH) stage(k0 + (ch + 1) * KC);
        GEMM_INNER(Wb, Ab, buf);
        if (ch + 1 < NCH) commit(buf ^ 1);
        buf ^= 1;
    }

    float* ps = g_psum[ks];
#pragma unroll
    for (int i = 0; i < 8; i++) {
        int t = t0 + 8 * ty + i;
#pragma unroll
        for (int m = 0; m < 4; m++) {
            float2 lo = *(float2*)&acc[i][2 * m];
            float2 hi = *(float2*)&acc[i][2 * m + 1];
            *(float4*)&ps[(size_t)t * E_ + 16 * tx + 4 * m] =
                make_float4(lo.x, lo.y, hi.x, hi.y);
        }
    }
}

// ---------------- combine K-split partials + background term ----------------
__global__ void k_combine(float* __restrict__ out) {
    int i  = blockIdx.x * 256 + threadIdx.x;
    int t  = i >> 5;
    int c4 = (i & 31) * 4;
    size_t off = (size_t)t * E_ + c4;
    float  beta = g_stats[t * 12 + 8];
    float4 cs = *(const float4*)&g_colsum[c4];
    float4 o = make_float4(beta * cs.x, beta * cs.y, beta * cs.z, beta * cs.w);
#pragma unroll
    for (int r = 0; r < KSPLIT; r++) {
        float4 a = *(const float4*)&g_psum[r][off];
        o.x += a.x; o.y += a.y; o.z += a.z; o.w += a.w;
    }
    *(float4*)&out[off] = o;
}

// ---------------- launch ----------------
extern "C" void kernel_launch(void* const* d_in, const int* in_sizes, int n_in,
                              void* d_out, int out_size) {
    const int*   src  = (const int*)  d_in[0];
    const float* X    = (const float*)d_in[1];
    const float* W    = (const float*)d_in[2];
    const float* edge = (const float*)d_in[3];
    const int*   rel  = (const int*)  d_in[4];
    float* out = (float*)d_out;

    cudaFuncSetAttribute(k_base,  cudaFuncAttributeMaxDynamicSharedMemorySize, BASE_SMEM);
    cudaFuncSetAttribute(k_final, cudaFuncAttributeMaxDynamicSharedMemorySize, FIN_SMEM);

    k_colsum1<<<40, 128>>>(W);
    k_colsum2<<<1, 128>>>();

    k_classify<<<(NTOK * NW) / 256, 256>>>(src, edge, rel);

    k_base<<<dim3(VPAD / 128, NTOK / 128), 128, BASE_SMEM>>>(X, W);   // 80 x 16

    k_stats<<<NTOK, 256>>>();

    k_final<<<dim3(NTOK / 128, KSPLIT), 128, FIN_SMEM>>>(W);          // 16 x 20

    k_combine<<<256, 256>>>(out);
    (void)in_sizes; (void)n_in; (void)out_size;
}

// round 17
// speedup vs baseline: 1.5644x; 1.5644x over previous
#include <cuda_runtime.h>
#include <cstdint>

#define V_     10000
#define VPAD   10240
#define E_     128
#define NTOK   2048
#define NR     8
#define NW     1250          // class words per token (V_/8)
#define NWP    1280          // padded words per token (VPAD/8)

#define KSPLIT 20
#define KQ     512           // 20*512 = 10240 = VPAD exactly

// ---------------- scratch (device globals; no allocations) ----------------
__device__ float    g_base[(size_t)NTOK * VPAD];     // q = exp(base)-1 (pad cols = 0)
__device__ uint32_t g_cls4[(size_t)NTOK * NWP];      // 4-bit classes, 8/word; pad = 0
__device__ float    g_colsum[E_];
__device__ float    g_part[40 * E_];
__device__ float    g_stats[NTOK * 12];              // K1[8], beta
__device__ float    g_psum[KSPLIT][(size_t)NTOK * E_];

__device__ __forceinline__ void fma2(unsigned long long& acc,
                                     unsigned long long a, unsigned long long b) {
    asm("fma.rn.f32x2 %0, %1, %2, %0;" : "+l"(acc) : "l"(a), "l"(b));
}

// ---------------- column sums of W (deterministic 2-stage) ----------------
__global__ void k_colsum1(const float* __restrict__ W) {
    int b = blockIdx.x, col = threadIdx.x;
    float s = 0.f;
    int v0 = b * 250;
    for (int v = v0; v < v0 + 250; v++) s += W[v * E_ + col];
    g_part[b * E_ + col] = s;
}
__global__ void k_colsum2() {
    int col = threadIdx.x;
    float s = 0.f;
    for (int b = 0; b < 40; b++) s += g_part[b * E_ + col];
    g_colsum[col] = s;
}

// ---------------- classification: rel/edge -> packed 4-bit classes ----------------
__global__ __launch_bounds__(256) void k_classify(
    const int*   __restrict__ src,
    const float* __restrict__ edge,
    const int*   __restrict__ rel)
{
    int idx = blockIdx.x * 256 + threadIdx.x;
    int t = idx / NW;
    int w = idx - t * NW;
    long s = src[t];
    int v0 = w * 8;
    const int*   rp = rel  + s * (long)V_ + v0;
    const float* ep = edge + s * (long)V_ + v0;
    uint32_t pack = 0;
#pragma unroll
    for (int h = 0; h < 2; h++) {
        int4   r4 = *(const int4*)  (rp + 4 * h);
        float4 e4 = *(const float4*)(ep + 4 * h);
        uint32_t cx = (r4.x >= 1 && r4.x <= 8 && e4.x > 0.f) ? (uint32_t)r4.x : 0u;
        uint32_t cy = (r4.y >= 1 && r4.y <= 8 && e4.y > 0.f) ? (uint32_t)r4.y : 0u;
        uint32_t cz = (r4.z >= 1 && r4.z <= 8 && e4.z > 0.f) ? (uint32_t)r4.z : 0u;
        uint32_t cw = (r4.w >= 1 && r4.w <= 8 && e4.w > 0.f) ? (uint32_t)r4.w : 0u;
        pack |= (cx | (cy << 4) | (cz << 8) | (cw << 12)) << (16 * h);
    }
    g_cls4[(size_t)t * NWP + w] = pack;
}

// ============== GEMM machinery: two empirically-best variants ==============
#define KC  16
#define AWB 260      // k_base A rows: duplicated (x,x) pairs, 128 tokens
#define AWF 132      // k_final A rows: duplicated pairs, 64 tokens

// ---- variant B (k_base, R12): 128tok x 128col CTA, 8tok x 16col/thread ----
#define GEMM_INNER_B(Wb, Ab, buf)                                            \
    _Pragma("unroll")                                                        \
    for (int kk = 0; kk < KC; kk++) {                                        \
        const float* wrow = &(Wb)[((buf) * KC + kk) * 128];                  \
        const float* arow = &(Ab)[((buf) * KC + kk) * AWB];                  \
        ulonglong2 wv[4], av[4];                                             \
        _Pragma("unroll")                                                    \
        for (int j = 0; j < 4; j++)                                          \
            wv[j] = *(const ulonglong2*)(wrow + 4 * (tx + 8 * j));           \
        _Pragma("unroll")                                                    \
        for (int j = 0; j < 4; j++)                                          \
            av[j] = *(const ulonglong2*)(arow + 4 * (16 * wq + 4 * j + s));  \
        _Pragma("unroll")                                                    \
        for (int j = 0; j < 4; j++) {                                        \
            unsigned long long a0 = av[j].x, a1 = av[j].y;                   \
            _Pragma("unroll")                                                \
            for (int jj = 0; jj < 4; jj++) {                                 \
                fma2(acc[2*j][2*jj],   a0, wv[jj].x);                        \
                fma2(acc[2*j][2*jj+1], a0, wv[jj].y);                        \
                fma2(acc[2*j+1][2*jj],   a1, wv[jj].x);                      \
                fma2(acc[2*j+1][2*jj+1], a1, wv[jj].y);                      \
            }                                                                \
        }                                                                    \
    }

// ---- variant F (k_final, R14): 64tok x 128col CTA, 4tok x 16col/thread ----
#define GEMM_INNER_F(Wb, Ab, buf)                                            \
    _Pragma("unroll")                                                        \
    for (int kk = 0; kk < KC; kk++) {                                        \
        const float* wrow = &(Wb)[((buf) * KC + kk) * 128];                  \
        const float* arow = &(Ab)[((buf) * KC + kk) * AWF];                  \
        ulonglong2 wv[4], av[2];                                             \
        _Pragma("unroll")                                                    \
        for (int j = 0; j < 4; j++)                                          \
            wv[j] = *(const ulonglong2*)(wrow + 4 * (tx + 8 * j));           \
        _Pragma("unroll")                                                    \
        for (int j = 0; j < 2; j++)                                          \
            av[j] = *(const ulonglong2*)(arow + 4 * (8 * wq + 4 * j + s));   \
        _Pragma("unroll")                                                    \
        for (int j = 0; j < 2; j++) {                                        \
            unsigned long long a0 = av[j].x, a1 = av[j].y;                   \
            _Pragma("unroll")                                                \
            for (int jj = 0; jj < 4; jj++) {                                 \
                fma2(acc[2*j][2*jj],   a0, wv[jj].x);                        \
                fma2(acc[2*j][2*jj+1], a0, wv[jj].y);                        \
                fma2(acc[2*j+1][2*jj],   a1, wv[jj].x);                      \
                fma2(acc[2*j+1][2*jj+1], a1, wv[jj].y);                      \
            }                                                                \
        }                                                                    \
    }

// ---------------- base GEMM: q = exp(X @ W^T) - 1  (R12 verbatim) ----------------
#define BASB_OFF  (2 * KC * 128)
#define BASE_SMEM ((BASB_OFF + 2 * KC * AWB) * 4)    // 49664 B

__global__ __launch_bounds__(128, 2) void k_base(
    const float* __restrict__ X,
    const float* __restrict__ W)
{
    extern __shared__ float smb[];
    float* Wb = smb;               // [buf*16 + kk][128]   kk = e index, col = v
    float* Ab = smb + BASB_OFF;    // [buf*16 + kk][260]   dup (x,x) per token

    int tid  = threadIdx.x;
    int vblk = blockIdx.x * 128;
    int t0   = blockIdx.y * 128;
    int wq = tid >> 5, s = (tid >> 3) & 3, tx = tid & 7;
    int gvW = vblk + tid;

    unsigned long long acc[8][8];
#pragma unroll
    for (int i = 0; i < 8; i++)
#pragma unroll
        for (int j = 0; j < 8; j++) acc[i][j] = 0ull;

    float4 wst[4], xst[4];
    auto stage = [&](int kc) {
#pragma unroll
        for (int j = 0; j < 4; j++)
            wst[j] = (gvW < V_) ? *(const float4*)&W[(size_t)gvW * E_ + kc + 4 * j]
                                : make_float4(0.f, 0.f, 0.f, 0.f);
#pragma unroll
        for (int j = 0; j < 4; j++)
            xst[j] = *(const float4*)&X[(size_t)(t0 + tid) * E_ + kc + 4 * j];
    };
    auto commit = [&](int buf) {
#pragma unroll
        for (int j = 0; j < 4; j++) {
            float* wr = &Wb[(buf * KC + 4 * j) * 128 + tid];
            wr[0]   = wst[j].x;
            wr[128] = wst[j].y;
            wr[256] = wst[j].z;
            wr[384] = wst[j].w;
        }
        float xs[16];
#pragma unroll
        for (int m = 0; m < 4; m++) {
            xs[4*m+0] = xst[m].x; xs[4*m+1] = xst[m].y;
            xs[4*m+2] = xst[m].z; xs[4*m+3] = xst[m].w;
        }
#pragma unroll
        for (int j = 0; j < 16; j++)
            *(float2*)&Ab[(buf * KC + j) * AWB + 2 * tid] = make_float2(xs[j], xs[j]);
    };

    stage(0);
    commit(0);
    int buf = 0;
    for (int ch = 0; ch < E_ / KC; ch++) {       // 8 chunks
        __syncthreads();
        if (ch + 1 < E_ / KC) stage((ch + 1) * KC);
        GEMM_INNER_B(Wb, Ab, buf);
        if (ch + 1 < E_ / KC) commit(buf ^ 1);
        buf ^= 1;
    }

#pragma unroll
    for (int i = 0; i < 8; i++) {
        int t = t0 + 32 * wq + 8 * (i >> 1) + 2 * s + (i & 1);
#pragma unroll
        for (int jj = 0; jj < 4; jj++) {
            float2 lo = *(float2*)&acc[i][2 * jj];
            float2 hi = *(float2*)&acc[i][2 * jj + 1];
            float4 q = make_float4(__expf(lo.x) - 1.f, __expf(lo.y) - 1.f,
                                   __expf(hi.x) - 1.f, __expf(hi.y) - 1.f);
            *(float4*)&g_base[(size_t)t * VPAD + vblk + 4 * (tx + 8 * jj)] = q;
        }
    }
}

// ---------------- per-(t,r) stats: single-copy lane-private smem RMW ----------------
#define CSTRIDE 33

__global__ __launch_bounds__(256) void k_stats() {
    __shared__ float2 accs[8][9 * CSTRIDE];
    __shared__ float  eArr[NR], dArr[NR], Bsh[8];

    int t   = blockIdx.x;
    int tid = threadIdx.x;
    int w   = tid >> 5, lane = tid & 31;

    for (int i = tid; i < 8 * 9 * CSTRIDE; i += 256)
        ((float2*)accs)[i] = make_float2(0.f, 0.f);
    __syncthreads();

    float B = 0.f;
    const float*    qRow = g_base + (size_t)t * VPAD;
    const uint32_t* cRow = g_cls4 + (size_t)t * NWP;

    for (int i = tid; i < NW; i += 256) {
        float4 qa = *(const float4*)(qRow + 8 * i);
        float4 qb = *(const float4*)(qRow + 8 * i + 4);
        uint32_t cw = cRow[i];
        float qs[8] = {qa.x, qa.y, qa.z, qa.w, qb.x, qb.y, qb.z, qb.w};
#pragma unroll
        for (int j = 0; j < 8; j++) {
            float q = qs[j];
            int   c = (cw >> (4 * j)) & 15;
            float b = __logf(fmaxf(q + 1.f, 1e-38f));
            B += b;
            float2* p = &accs[w][c * CSTRIDE + lane];
            float2 o = *p;
            o.x += q;
            o.y = fmaf(q, b, o.y);
            *p = o;
        }
    }
#pragma unroll
    for (int o = 16; o; o >>= 1) B += __shfl_xor_sync(0xFFFFFFFFu, B, o);
    if (lane == 0) Bsh[w] = B;
    __syncthreads();

    {
        float2 s = make_float2(0.f, 0.f);
#pragma unroll
        for (int ww = 0; ww < 8; ww++) {
            float2 a = accs[ww][(w + 1) * CSTRIDE + lane];
            s.x += a.x; s.y += a.y;
        }
#pragma unroll
        for (int o = 16; o; o >>= 1) {
            s.x += __shfl_xor_sync(0xFFFFFFFFu, s.x, o);
            s.y += __shfl_xor_sync(0xFFFFFFFFu, s.y, o);
        }
        if (lane == 0) { eArr[w] = s.x; dArr[w] = s.y; }
    }
    __syncthreads();

    if (tid == 0) {
        float Bt = 0.f;
#pragma unroll
        for (int k = 0; k < 8; k++) Bt += Bsh[k];
        float sc[NR], Zv[NR];
#pragma unroll
        for (int r = 0; r < NR; r++) {
            float Z = (float)V_ + eArr[r];
            Zv[r] = Z;
            sc[r] = (dArr[r] + Bt) / Z;
        }
        float mx = sc[0];
#pragma unroll
        for (int r = 1; r < NR; r++) mx = fmaxf(mx, sc[r]);
        float es[NR], ss = 0.f;
#pragma unroll
        for (int r = 0; r < NR; r++) { es[r] = __expf(sc[r] - mx); ss += es[r]; }
        float inv = 1.f / ss;
        float beta = 0.f;
        float* st = g_stats + t * 12;
#pragma unroll
        for (int r = 0; r < NR; r++) {
            float K1 = es[r] * inv / Zv[r];
            st[r] = K1;
            beta += K1;
        }
        st[8] = beta;
    }
}

// ---------------- final GEMM (R14 verbatim): psum = gamma @ W ----------------
#define BASF_OFF  (2 * KC * 128)
#define FK1_OFF   (BASF_OFF + 2 * KC * AWF)
#define FIN_SMEM  ((FK1_OFF + 8 * 64) * 4)          // 35328 B

__global__ __launch_bounds__(128, 3) void k_final(const float* __restrict__ W) {
    extern __shared__ float smf[];
    float* Wb  = smf;              // [buf*16 + kk][128]  kk = v index, col = e
    float* Ab  = smf + BASF_OFF;   // [buf*16 + kk][132]  dup gamma, 64 tokens
    float* K1s = smf + FK1_OFF;    // [r][64] transposed

    int tid = threadIdx.x;
    int t0  = blockIdx.x * 64;
    int ks  = blockIdx.y;
    int k0  = ks * KQ;
    int wq = tid >> 5, s = (tid >> 3) & 3, tx = tid & 7;
    int ttA = tid >> 1, kA = (tid & 1) * 8;

    if (tid < 64) {
        float4 k1a = *(const float4*)&g_stats[(t0 + tid) * 12];
        float4 k1b = *(const float4*)&g_stats[(t0 + tid) * 12 + 4];
        K1s[0 * 64 + tid] = k1a.x; K1s[1 * 64 + tid] = k1a.y;
        K1s[2 * 64 + tid] = k1a.z; K1s[3 * 64 + tid] = k1a.w;
        K1s[4 * 64 + tid] = k1b.x; K1s[5 * 64 + tid] = k1b.y;
        K1s[6 * 64 + tid] = k1b.z; K1s[7 * 64 + tid] = k1b.w;
    }
    __syncthreads();

    unsigned long long acc[4][8];
#pragma unroll
    for (int i = 0; i < 4; i++)
#pragma unroll
        for (int j = 0; j < 8; j++) acc[i][j] = 0ull;

    float4   wst[4], qst[2];
    uint32_t cst;

    auto stage = [&](int kc) {
#pragma unroll
        for (int j = 0; j < 4; j++) {
            int p  = tid + 128 * j;
            int v  = p >> 5;
            int e4 = (p & 31) * 4;
            int gv = kc + v;
            wst[j] = (gv < V_) ? *(const float4*)&W[(size_t)gv * E_ + e4]
                               : make_float4(0.f, 0.f, 0.f, 0.f);
        }
        size_t off = (size_t)(t0 + ttA) * VPAD + kc + kA;
        qst[0] = *(const float4*)(g_base + off);
        qst[1] = *(const float4*)(g_base + off + 4);
        cst = g_cls4[(size_t)(t0 + ttA) * NWP + (kc >> 3) + (tid & 1)];
    };
    auto commit = [&](int buf) {
#pragma unroll
        for (int j = 0; j < 4; j++) {
            int p  = tid + 128 * j;
            int v  = p >> 5;
            int e4 = (p & 31) * 4;
            *(float4*)&Wb[(buf * KC + v) * 128 + e4] = wst[j];
        }
        float qs[8] = {qst[0].x, qst[0].y, qst[0].z, qst[0].w,
                       qst[1].x, qst[1].y, qst[1].z, qst[1].w};
#pragma unroll
        for (int m = 0; m < 8; m++) {
            int cc = (cst >> (4 * m)) & 15;
            float g = cc ? K1s[(cc - 1) * 64 + ttA] * qs[m] : 0.f;
            *(float2*)&Ab[(buf * KC + kA + m) * AWF + 2 * ttA] = make_float2(g, g);
        }
    };

    stage(k0);
    commit(0);
    int buf = 0;
    const int NCH = KQ / KC;     // 32
    for (int ch = 0; ch < NCH; ch++) {
        __syncthreads();
        if (ch + 1 < NCH) stage(k0 + (ch + 1) * KC);
        GEMM_INNER_F(Wb, Ab, buf);
        if (ch + 1 < NCH) commit(buf ^ 1);
        buf ^= 1;
    }

    float* ps = g_psum[ks];
#pragma unroll
    for (int i = 0; i < 4; i++) {
        int t = t0 + 16 * wq + 8 * (i >> 1) + 2 * s + (i & 1);
#pragma unroll
        for (int jj = 0; jj < 4; jj++) {
            float2 lo = *(float2*)&acc[i][2 * jj];
            float2 hi = *(float2*)&acc[i][2 * jj + 1];
            *(float4*)&ps[(size_t)t * E_ + 4 * (tx + 8 * jj)] =
                make_float4(lo.x, lo.y, hi.x, hi.y);
        }
    }
}

// ---------------- combine K-split partials + background term ----------------
__global__ void k_combine(float* __restrict__ out) {
    int i  = blockIdx.x * 256 + threadIdx.x;
    int t  = i >> 5;
    int c4 = (i & 31) * 4;
    size_t off = (size_t)t * E_ + c4;
    float  beta = g_stats[t * 12 + 8];
    float4 cs = *(const float4*)&g_colsum[c4];
    float4 o = make_float4(beta * cs.x, beta * cs.y, beta * cs.z, beta * cs.w);
#pragma unroll
    for (int r = 0; r < KSPLIT; r++) {
        float4 a = *(const float4*)&g_psum[r][off];
        o.x += a.x; o.y += a.y; o.z += a.z; o.w += a.w;
    }
    *(float4*)&out[off] = o;
}

// ---------------- launch ----------------
extern "C" void kernel_launch(void* const* d_in, const int* in_sizes, int n_in,
                              void* d_out, int out_size) {
    const int*   src  = (const int*)  d_in[0];
    const float* X    = (const float*)d_in[1];
    const float* W    = (const float*)d_in[2];
    const float* edge = (const float*)d_in[3];
    const int*   rel  = (const int*)  d_in[4];
    float* out = (float*)d_out;

    cudaFuncSetAttribute(k_base,  cudaFuncAttributeMaxDynamicSharedMemorySize, BASE_SMEM);
    cudaFuncSetAttribute(k_final, cudaFuncAttributeMaxDynamicSharedMemorySize, FIN_SMEM);

    k_colsum1<<<40, 128>>>(W);
    k_colsum2<<<1, 128>>>();

    k_classify<<<(NTOK * NW) / 256, 256>>>(src, edge, rel);

    k_base<<<dim3(VPAD / 128, NTOK / 128), 128, BASE_SMEM>>>(X, W);   // 80 x 16

    k_stats<<<NTOK, 256>>>();

    k_final<<<dim3(NTOK / 64, KSPLIT), 128, FIN_SMEM>>>(W);           // 32 x 20

    k_combine<<<256, 256>>>(out);
    (void)in_sizes; (void)n_in; (void)out_size;
}